// round 11
// baseline (speedup 1.0000x reference)
#include <cuda_runtime.h>
#include <cuda_fp16.h>
#include <cstdint>

#define N_NODES 100000
#define N_USERS 60000
#define N_EDGES 1200000
#define D 64
#define CAP 64   // slots per row; P(Poisson(12) >= 64) ~ 1e-30

// Scratch (static device globals — no allocation allowed in kernel_launch)
__device__ int   g_cnt[N_NODES];
__device__ float g_dinv[N_NODES];
__device__ __align__(16) int2     g_edge[N_NODES * CAP]; // slot CSR: (col, coef-bits)
__device__ __align__(16) float    g_h[N_NODES * D];      // X @ W, fp32 (self term)
__device__ __align__(16) uint32_t g_hh[N_NODES * 32];    // X @ W, half2 (gather copy)
__device__ __align__(16) float    g_t[N_NODES * D];      // layer-1 activated output

// edge_index is int32 (JAX x64-disabled downcasts the int64 request).
// Slot-CSR build: one pass, no histogram / prefix scan.
__global__ void k_bin(const int* __restrict__ ei) {
    int e = blockIdx.x * blockDim.x + threadIdx.x;
    if (e >= N_EDGES) return;
    int s = ei[e];
    int d = ei[N_EDGES + e];
    int pos = atomicAdd(&g_cnt[d], 1);
    if (pos < CAP) g_edge[d * CAP + pos].x = s;
}

__global__ void k_dinv() {
    int i = blockIdx.x * blockDim.x + threadIdx.x;
    if (i < N_NODES) g_dinv[i] = rsqrtf((float)g_cnt[i] + 1.0f);
}

// Fill coef into slots: one warp per row, lanes cover slots. Runs once,
// benefits both SpMM layers (coef = dinv[src] * dinv[dst]).
__global__ void __launch_bounds__(128) k_coef() {
    int row  = (blockIdx.x * blockDim.x + threadIdx.x) >> 5;
    int lane = threadIdx.x & 31;
    if (row >= N_NODES) return;
    int len = g_cnt[row];
    if (len > CAP) len = CAP;
    float di = g_dinv[row];
    for (int e = lane; e < len; e += 32) {
        int c = g_edge[row * CAP + e].x;
        float cf = g_dinv[c] * di;
        g_edge[row * CAP + e] = make_int2(c, __float_as_int(cf));
    }
}

// ---------------- tf32 MMA GEMM (3xtf32 split for fp32 accuracy) ----------------
__device__ __forceinline__ uint32_t f2tf(float v) {
    uint32_t r;
    asm("cvt.rna.tf32.f32 %0, %1;" : "=r"(r) : "f"(v));
    return r;
}
__device__ __forceinline__ void split_tf(float v, uint32_t& hi, uint32_t& lo) {
    hi = f2tf(v);
    lo = f2tf(v - __uint_as_float(hi));
}
__device__ __forceinline__ void mma8(float4& d, const uint32_t* a, uint32_t b0, uint32_t b1) {
    asm volatile(
        "mma.sync.aligned.m16n8k8.row.col.f32.tf32.tf32.f32 "
        "{%0,%1,%2,%3}, {%4,%5,%6,%7}, {%8,%9}, {%0,%1,%2,%3};"
        : "+f"(d.x), "+f"(d.y), "+f"(d.z), "+f"(d.w)
        : "r"(a[0]), "r"(a[1]), "r"(a[2]), "r"(a[3]), "r"(b0), "r"(b1));
}

// H = X @ W (100000x64 @ 64x64). 128 threads = 4 warps; 16 rows/warp.
// Writes fp32 g_h and half2 g_hh (both unscaled). No CSR dependency.
template <int SRC>  // 0: X = input x, 1: X = g_t
__global__ void __launch_bounds__(128) k_gemm(const float* __restrict__ Xin,
                                              const float* __restrict__ W) {
    __shared__ __align__(16) float sX[64 * 68];
    __shared__ __align__(16) float sW[64 * 72];
    const float* X = (SRC == 0) ? Xin : (const float*)g_t;
    int tid = threadIdx.x, warp = tid >> 5, lane = tid & 31;
    int g = lane >> 2, tq = lane & 3;
    int rowbase = blockIdx.x * 64;

    for (int i = tid; i < 1024; i += 128) {
        int k = i >> 4, c4 = (i & 15) << 2;
        float4 w = reinterpret_cast<const float4*>(W)[i];
        *reinterpret_cast<float4*>(&sW[k * 72 + c4]) = w;
    }
    for (int i = tid; i < 1024; i += 128) {
        int r = i >> 4, c4i = i & 15;
        int gr = rowbase + r;
        float4 v = (gr < N_NODES)
                       ? reinterpret_cast<const float4*>(X + (size_t)gr * D)[c4i]
                       : make_float4(0.f, 0.f, 0.f, 0.f);
        *reinterpret_cast<float4*>(&sX[r * 68 + (c4i << 2)]) = v;
    }
    __syncthreads();

    int wr = warp * 16;
    float4 acc[8];
#pragma unroll
    for (int nt = 0; nt < 8; nt++) acc[nt] = make_float4(0.f, 0.f, 0.f, 0.f);

#pragma unroll
    for (int kt = 0; kt < 8; kt++) {
        uint32_t ah[4], al[4];
        {
            float a0 = sX[(wr + g) * 68 + kt * 8 + tq];
            float a1 = sX[(wr + g + 8) * 68 + kt * 8 + tq];
            float a2 = sX[(wr + g) * 68 + kt * 8 + tq + 4];
            float a3 = sX[(wr + g + 8) * 68 + kt * 8 + tq + 4];
            split_tf(a0, ah[0], al[0]);
            split_tf(a1, ah[1], al[1]);
            split_tf(a2, ah[2], al[2]);
            split_tf(a3, ah[3], al[3]);
        }
#pragma unroll
        for (int nt = 0; nt < 8; nt++) {
            float b0f = sW[(kt * 8 + tq) * 72 + nt * 8 + g];
            float b1f = sW[(kt * 8 + tq + 4) * 72 + nt * 8 + g];
            uint32_t bh0, bl0, bh1, bl1;
            split_tf(b0f, bh0, bl0);
            split_tf(b1f, bh1, bl1);
            mma8(acc[nt], ah, bh0, bh1);
            mma8(acc[nt], al, bh0, bh1);
            mma8(acc[nt], ah, bl0, bl1);
        }
    }

    int r0 = rowbase + wr + g;
    int r1 = r0 + 8;
#pragma unroll
    for (int nt = 0; nt < 8; nt++) {
        int c = nt * 8 + tq * 2;
        if (r0 < N_NODES) {
            *reinterpret_cast<float2*>(g_h + (size_t)r0 * D + c) = make_float2(acc[nt].x, acc[nt].y);
            half2 hx = __floats2half2_rn(acc[nt].x, acc[nt].y);
            g_hh[r0 * 32 + (c >> 1)] = *reinterpret_cast<uint32_t*>(&hx);
        }
        if (r1 < N_NODES) {
            *reinterpret_cast<float2*>(g_h + (size_t)r1 * D + c) = make_float2(acc[nt].z, acc[nt].w);
            half2 hx = __floats2half2_rn(acc[nt].z, acc[nt].w);
            g_hh[r1 * 32 + (c >> 1)] = *reinterpret_cast<uint32_t*>(&hx);
        }
    }
}

// ---------------- SpMM: one warp per dst row, slot CSR (col,coef), fp16 gathers ---------
// R7's proven lean loop: one LDG.64 per edge gets col+coef; 8-wide batches + serial tail.
// MODE 1: relu -> g_t. MODE 2: final -> out[row] and out[N_NODES + row] (dup copy).
template <int MODE>
__global__ void __launch_bounds__(128) k_spmm(const float* __restrict__ bias,
                                              float* __restrict__ out) {
    int warp = (blockIdx.x * blockDim.x + threadIdx.x) >> 5;
    int lane = threadIdx.x & 31;
    if (warp >= N_NODES) return;
    int row = warp;
    float di = g_dinv[row];
    float sc = di * di;
    int len = g_cnt[row];
    if (len > CAP) len = CAP;
    float2 hv = reinterpret_cast<const float2*>(g_h + (size_t)row * D)[lane];
    float ax = hv.x * sc, ay = hv.y * sc;
    const int2* edges = g_edge + row * CAP;
    int e = 0;
    for (; e + 8 <= len; e += 8) {
        int2 p[8];
        uint32_t v[8];
#pragma unroll
        for (int j = 0; j < 8; j++) p[j] = edges[e + j];
#pragma unroll
        for (int j = 0; j < 8; j++) v[j] = g_hh[p[j].x * 32 + lane];
#pragma unroll
        for (int j = 0; j < 8; j++) {
            float2 f = __half22float2(*reinterpret_cast<half2*>(&v[j]));
            float c = __int_as_float(p[j].y);
            ax += f.x * c;
            ay += f.y * c;
        }
    }
    for (; e < len; e++) {
        int2 p = edges[e];
        uint32_t vv = g_hh[p.x * 32 + lane];
        float2 f = __half22float2(*reinterpret_cast<half2*>(&vv));
        float c = __int_as_float(p.y);
        ax += f.x * c;
        ay += f.y * c;
    }
    float2 bv = reinterpret_cast<const float2*>(bias)[lane];
    ax += bv.x;
    ay += bv.y;
    if (MODE == 1) {
        float2 r = make_float2(fmaxf(ax, 0.f), fmaxf(ay, 0.f));
        reinterpret_cast<float2*>(g_t + (size_t)row * D)[lane] = r;
    } else {
        float2 r = make_float2(ax, ay);
        reinterpret_cast<float2*>(out + (size_t)row * D)[lane] = r;
        reinterpret_cast<float2*>(out + (size_t)(N_NODES + row) * D)[lane] = r;
    }
}

extern "C" void kernel_launch(void* const* d_in, const int* in_sizes, int n_in,
                              void* d_out, int out_size) {
    const float* x  = (const float*)d_in[0];
    const int*   ei = (const int*)d_in[1];
    const float* W1 = (const float*)d_in[2];
    const float* b1 = (const float*)d_in[3];
    const float* W2 = (const float*)d_in[4];
    const float* b2 = (const float*)d_in[5];
    float* out = (float*)d_out;

    static cudaStream_t s1 = nullptr;
    static cudaEvent_t ev_fork = nullptr, ev_join = nullptr;
    if (s1 == nullptr) {
        cudaStreamCreateWithFlags(&s1, cudaStreamNonBlocking);
        cudaEventCreateWithFlags(&ev_fork, cudaEventDisableTiming);
        cudaEventCreateWithFlags(&ev_join, cudaEventDisableTiming);
    }

    void* cnt_ptr = nullptr;
    cudaGetSymbolAddress(&cnt_ptr, g_cnt);

    // Fork: gemm0 runs on s1 concurrently with the slot-CSR build on the main stream.
    cudaEventRecord(ev_fork, 0);
    cudaStreamWaitEvent(s1, ev_fork, 0);
    k_gemm<0><<<(N_NODES + 63) / 64, 128, 0, s1>>>(x, W1);      // g_h/g_hh = x @ W1
    cudaEventRecord(ev_join, s1);

    // Slot-CSR build on the main stream: memset -> bin -> dinv -> coef.
    cudaMemsetAsync(cnt_ptr, 0, N_NODES * sizeof(int));
    k_bin<<<(N_EDGES + 255) / 256, 256>>>(ei);
    k_dinv<<<(N_NODES + 255) / 256, 256>>>();
    k_coef<<<(N_NODES * 32 + 127) / 128, 128>>>();

    // Join: spmm1 needs both the slot CSR and gemm0's output.
    cudaStreamWaitEvent(0, ev_join, 0);
    k_spmm<1><<<(N_NODES * 32 + 127) / 128, 128>>>(b1, out);    // g_t = relu(gcn1)
    k_gemm<1><<<(N_NODES + 63) / 64, 128>>>(x, W2);             // g_h/g_hh = g_t @ W2
    k_spmm<2><<<(N_NODES * 32 + 127) / 128, 128>>>(b2, out);    // out = [h; h]
}

// round 12
// speedup vs baseline: 1.0400x; 1.0400x over previous
#include <cuda_runtime.h>
#include <cuda_fp16.h>
#include <cstdint>

#define N_NODES 100000
#define N_USERS 60000
#define N_EDGES 1200000
#define D 64
#define CAP 64   // slots per row; P(Poisson(12) >= 64) ~ 1e-30

// Scratch (static device globals — no allocation allowed in kernel_launch)
__device__ int   g_cnt[N_NODES];
__device__ float g_dinv[N_NODES];
__device__ __align__(16) int      g_ecol[N_NODES * CAP]; // slot CSR: col only (4B)
__device__ __align__(16) float    g_h[N_NODES * D];      // X @ W, fp32, unscaled (self term)
__device__ __align__(16) uint32_t g_hh[N_NODES * 32];    // dinv*h, half2 (gather copy)
__device__ __align__(16) float    g_t[N_NODES * D];      // layer-1 activated output

// edge_index is int32 (JAX x64-disabled downcasts the int64 request).
// Slot-CSR build: one pass, no histogram / prefix scan, 4B scattered stores.
__global__ void k_bin(const int* __restrict__ ei) {
    int e = blockIdx.x * blockDim.x + threadIdx.x;
    if (e >= N_EDGES) return;
    int s = ei[e];
    int d = ei[N_EDGES + e];
    int pos = atomicAdd(&g_cnt[d], 1);
    if (pos < CAP) g_ecol[d * CAP + pos] = s;
}

__global__ void k_dinv() {
    int i = blockIdx.x * blockDim.x + threadIdx.x;
    if (i < N_NODES) g_dinv[i] = rsqrtf((float)g_cnt[i] + 1.0f);
}

// Scale layer-1 gather copy in place: g_hh[row] *= dinv[row]. Streaming, ~26 MB rw.
// fp32 math so the only half rounding is the final store.
__global__ void k_scale() {
    int i = blockIdx.x * blockDim.x + threadIdx.x;
    if (i >= N_NODES * 32) return;
    int row = i >> 5;
    float di = g_dinv[row];
    uint32_t u = g_hh[i];
    float2 f = __half22float2(*reinterpret_cast<half2*>(&u));
    half2 r = __floats2half2_rn(f.x * di, f.y * di);
    g_hh[i] = *reinterpret_cast<uint32_t*>(&r);
}

// ---------------- tf32 MMA GEMM (3xtf32 split for fp32 accuracy) ----------------
__device__ __forceinline__ uint32_t f2tf(float v) {
    uint32_t r;
    asm("cvt.rna.tf32.f32 %0, %1;" : "=r"(r) : "f"(v));
    return r;
}
__device__ __forceinline__ void split_tf(float v, uint32_t& hi, uint32_t& lo) {
    hi = f2tf(v);
    lo = f2tf(v - __uint_as_float(hi));
}
__device__ __forceinline__ void mma8(float4& d, const uint32_t* a, uint32_t b0, uint32_t b1) {
    asm volatile(
        "mma.sync.aligned.m16n8k8.row.col.f32.tf32.tf32.f32 "
        "{%0,%1,%2,%3}, {%4,%5,%6,%7}, {%8,%9}, {%0,%1,%2,%3};"
        : "+f"(d.x), "+f"(d.y), "+f"(d.z), "+f"(d.w)
        : "r"(a[0]), "r"(a[1]), "r"(a[2]), "r"(a[3]), "r"(b0), "r"(b1));
}

// H = X @ W (100000x64 @ 64x64). 128 threads = 4 warps; 16 rows/warp.
// Epilogue: g_h = h (fp32, unscaled). g_hh = half2(h) if SCALE==0 (dinv not yet
// known; k_scale fixes it up), half2(dinv[r]*h) if SCALE==1.
template <int SRC, int SCALE>  // SRC 0: X = input x, 1: X = g_t
__global__ void __launch_bounds__(128) k_gemm(const float* __restrict__ Xin,
                                              const float* __restrict__ W) {
    __shared__ __align__(16) float sX[64 * 68];
    __shared__ __align__(16) float sW[64 * 72];
    const float* X = (SRC == 0) ? Xin : (const float*)g_t;
    int tid = threadIdx.x, warp = tid >> 5, lane = tid & 31;
    int g = lane >> 2, tq = lane & 3;
    int rowbase = blockIdx.x * 64;

    for (int i = tid; i < 1024; i += 128) {
        int k = i >> 4, c4 = (i & 15) << 2;
        float4 w = reinterpret_cast<const float4*>(W)[i];
        *reinterpret_cast<float4*>(&sW[k * 72 + c4]) = w;
    }
    for (int i = tid; i < 1024; i += 128) {
        int r = i >> 4, c4i = i & 15;
        int gr = rowbase + r;
        float4 v = (gr < N_NODES)
                       ? reinterpret_cast<const float4*>(X + (size_t)gr * D)[c4i]
                       : make_float4(0.f, 0.f, 0.f, 0.f);
        *reinterpret_cast<float4*>(&sX[r * 68 + (c4i << 2)]) = v;
    }
    __syncthreads();

    int wr = warp * 16;
    float4 acc[8];
#pragma unroll
    for (int nt = 0; nt < 8; nt++) acc[nt] = make_float4(0.f, 0.f, 0.f, 0.f);

#pragma unroll
    for (int kt = 0; kt < 8; kt++) {
        uint32_t ah[4], al[4];
        {
            float a0 = sX[(wr + g) * 68 + kt * 8 + tq];
            float a1 = sX[(wr + g + 8) * 68 + kt * 8 + tq];
            float a2 = sX[(wr + g) * 68 + kt * 8 + tq + 4];
            float a3 = sX[(wr + g + 8) * 68 + kt * 8 + tq + 4];
            split_tf(a0, ah[0], al[0]);
            split_tf(a1, ah[1], al[1]);
            split_tf(a2, ah[2], al[2]);
            split_tf(a3, ah[3], al[3]);
        }
#pragma unroll
        for (int nt = 0; nt < 8; nt++) {
            float b0f = sW[(kt * 8 + tq) * 72 + nt * 8 + g];
            float b1f = sW[(kt * 8 + tq + 4) * 72 + nt * 8 + g];
            uint32_t bh0, bl0, bh1, bl1;
            split_tf(b0f, bh0, bl0);
            split_tf(b1f, bh1, bl1);
            mma8(acc[nt], ah, bh0, bh1);
            mma8(acc[nt], al, bh0, bh1);
            mma8(acc[nt], ah, bl0, bl1);
        }
    }

    int r0 = rowbase + wr + g;
    int r1 = r0 + 8;
    float s0 = 1.f, s1 = 1.f;
    if (SCALE == 1) {
        s0 = (r0 < N_NODES) ? g_dinv[r0] : 0.f;
        s1 = (r1 < N_NODES) ? g_dinv[r1] : 0.f;
    }
#pragma unroll
    for (int nt = 0; nt < 8; nt++) {
        int c = nt * 8 + tq * 2;
        if (r0 < N_NODES) {
            *reinterpret_cast<float2*>(g_h + (size_t)r0 * D + c) = make_float2(acc[nt].x, acc[nt].y);
            half2 hx = __floats2half2_rn(acc[nt].x * s0, acc[nt].y * s0);
            g_hh[r0 * 32 + (c >> 1)] = *reinterpret_cast<uint32_t*>(&hx);
        }
        if (r1 < N_NODES) {
            *reinterpret_cast<float2*>(g_h + (size_t)r1 * D + c) = make_float2(acc[nt].z, acc[nt].w);
            half2 hx = __floats2half2_rn(acc[nt].z * s1, acc[nt].w * s1);
            g_hh[r1 * 32 + (c >> 1)] = *reinterpret_cast<uint32_t*>(&hx);
        }
    }
}

// ---------------- SpMM: one warp per dst row, col-only slots, pre-scaled gathers --------
// out = dinv[row] * (sum_c hh_c) + dinv[row]^2 * h_row + bias    (hh_c = dinv[c]*h_c)
// R7's proven loop shape: unpredicated 8-wide batches + serial tail. No coef anywhere.
// MODE 1: relu -> g_t. MODE 2: final -> out[row] and out[N_NODES + row] (dup copy).
template <int MODE>
__global__ void __launch_bounds__(128) k_spmm(const float* __restrict__ bias,
                                              float* __restrict__ out) {
    int warp = (blockIdx.x * blockDim.x + threadIdx.x) >> 5;
    int lane = threadIdx.x & 31;
    if (warp >= N_NODES) return;
    int row = warp;
    float di = g_dinv[row];
    int len = g_cnt[row];
    if (len > CAP) len = CAP;
    const int* cols = g_ecol + row * CAP;
    float ax = 0.f, ay = 0.f;
    int e = 0;
    for (; e + 8 <= len; e += 8) {
        int c[8];
        uint32_t v[8];
#pragma unroll
        for (int j = 0; j < 8; j++) c[j] = cols[e + j];
#pragma unroll
        for (int j = 0; j < 8; j++) v[j] = g_hh[c[j] * 32 + lane];
#pragma unroll
        for (int j = 0; j < 8; j++) {
            float2 f = __half22float2(*reinterpret_cast<half2*>(&v[j]));
            ax += f.x;
            ay += f.y;
        }
    }
    for (; e < len; e++) {
        uint32_t vv = g_hh[cols[e] * 32 + lane];
        float2 f = __half22float2(*reinterpret_cast<half2*>(&vv));
        ax += f.x;
        ay += f.y;
    }
    float2 hv = reinterpret_cast<const float2*>(g_h + (size_t)row * D)[lane];
    float2 bv = reinterpret_cast<const float2*>(bias)[lane];
    float sc = di * di;
    ax = ax * di + hv.x * sc + bv.x;
    ay = ay * di + hv.y * sc + bv.y;
    if (MODE == 1) {
        float2 r = make_float2(fmaxf(ax, 0.f), fmaxf(ay, 0.f));
        reinterpret_cast<float2*>(g_t + (size_t)row * D)[lane] = r;
    } else {
        float2 r = make_float2(ax, ay);
        reinterpret_cast<float2*>(out + (size_t)row * D)[lane] = r;
        reinterpret_cast<float2*>(out + (size_t)(N_NODES + row) * D)[lane] = r;
    }
}

extern "C" void kernel_launch(void* const* d_in, const int* in_sizes, int n_in,
                              void* d_out, int out_size) {
    const float* x  = (const float*)d_in[0];
    const int*   ei = (const int*)d_in[1];
    const float* W1 = (const float*)d_in[2];
    const float* b1 = (const float*)d_in[3];
    const float* W2 = (const float*)d_in[4];
    const float* b2 = (const float*)d_in[5];
    float* out = (float*)d_out;

    static cudaStream_t s1 = nullptr;
    static cudaEvent_t ev_fork = nullptr, ev_join = nullptr;
    if (s1 == nullptr) {
        cudaStreamCreateWithFlags(&s1, cudaStreamNonBlocking);
        cudaEventCreateWithFlags(&ev_fork, cudaEventDisableTiming);
        cudaEventCreateWithFlags(&ev_join, cudaEventDisableTiming);
    }

    void* cnt_ptr = nullptr;
    cudaGetSymbolAddress(&cnt_ptr, g_cnt);

    // Fork: gemm0 (unscaled epilogue) runs on s1 concurrently with the CSR build.
    cudaEventRecord(ev_fork, 0);
    cudaStreamWaitEvent(s1, ev_fork, 0);
    k_gemm<0, 0><<<(N_NODES + 63) / 64, 128, 0, s1>>>(x, W1);   // g_h/g_hh = x @ W1
    cudaEventRecord(ev_join, s1);

    // Slot-CSR build on the main stream: memset -> bin -> dinv. No hist/scan/coef.
    cudaMemsetAsync(cnt_ptr, 0, N_NODES * sizeof(int));
    k_bin<<<(N_EDGES + 255) / 256, 256>>>(ei);
    k_dinv<<<(N_NODES + 255) / 256, 256>>>();

    // Join, then scale layer-1 gather copy by dinv (needs gemm0 + dinv).
    cudaStreamWaitEvent(0, ev_join, 0);
    k_scale<<<(N_NODES * 32 + 255) / 256, 256>>>();

    k_spmm<1><<<(N_NODES * 32 + 127) / 128, 128>>>(b1, out);    // g_t = relu(gcn1)
    k_gemm<1, 1><<<(N_NODES + 63) / 64, 128>>>(x, W2);          // g_h/g_hh = g_t @ W2 (scaled)
    k_spmm<2><<<(N_NODES * 32 + 127) / 128, 128>>>(b2, out);    // out = [h; h]
}

// round 13
// speedup vs baseline: 1.1086x; 1.0660x over previous
#include <cuda_runtime.h>
#include <cuda_fp16.h>
#include <cstdint>

#define N_NODES 100000
#define N_USERS 60000
#define N_EDGES 1200000
#define D 64
#define NB 98   // ceil(100000/1024) scan blocks

// Scratch (static device globals — no allocation allowed in kernel_launch)
__device__ int   g_cnt[N_NODES];
__device__ int   g_rowptr[N_NODES + 1];
__device__ int   g_fill[N_NODES];
__device__ float g_dinv[N_NODES];
__device__ int   g_bsum[NB];
__device__ __align__(16) int2     g_edge[N_EDGES];     // (col*32, coef-bits)
__device__ __align__(16) float    g_h[N_NODES * D];    // X @ W, fp32 (self term)
__device__ __align__(16) uint32_t g_hh[N_NODES * 32];  // X @ W, half2 (gather copy)
__device__ __align__(16) float    g_t[N_NODES * D];    // layer-1 activated output

// edge_index is int32 (JAX x64-disabled downcasts the int64 request).
__global__ void k_hist(const int* __restrict__ ei) {
    int e = blockIdx.x * blockDim.x + threadIdx.x;
    if (e < N_EDGES) atomicAdd(&g_cnt[ei[N_EDGES + e]], 1);
}

// Pass A: per-1024-chunk sums.
__global__ void k_reduce() {
    __shared__ int wsum[32];
    int tid = threadIdx.x, lane = tid & 31, w = tid >> 5;
    int i = blockIdx.x * 1024 + tid;
    int v = (i < N_NODES) ? g_cnt[i] : 0;
    int s = v;
#pragma unroll
    for (int o = 16; o > 0; o >>= 1) s += __shfl_down_sync(0xffffffffu, s, o);
    if (lane == 0) wsum[w] = s;
    __syncthreads();
    if (w == 0) {
        int t = wsum[lane];
#pragma unroll
        for (int o = 16; o > 0; o >>= 1) t += __shfl_down_sync(0xffffffffu, t, o);
        if (lane == 0) g_bsum[blockIdx.x] = t;
    }
}

// Pass B (fused): every block redundantly computes its global offset from the 98
// block sums (warp 0), then local exclusive scan of its chunk -> rowptr/fill/dinv.
__global__ void k_scanf() {
    __shared__ int wsum[32];
    __shared__ int s_boff;
    int tid = threadIdx.x, lane = tid & 31, w = tid >> 5;
    if (w == 0) {
        int s = 0;
        for (int j = lane; j < blockIdx.x; j += 32) s += g_bsum[j];
#pragma unroll
        for (int o = 16; o > 0; o >>= 1) s += __shfl_down_sync(0xffffffffu, s, o);
        if (lane == 0) s_boff = s;
    }
    __syncthreads();
    int i = blockIdx.x * 1024 + tid;
    int v = (i < N_NODES) ? g_cnt[i] : 0;
    if (i < N_NODES) g_dinv[i] = rsqrtf((float)v + 1.0f);
    int inc = v;
#pragma unroll
    for (int o = 1; o < 32; o <<= 1) {
        int t = __shfl_up_sync(0xffffffffu, inc, o);
        if (lane >= o) inc += t;
    }
    if (lane == 31) wsum[w] = inc;
    __syncthreads();
    if (w == 0) {
        int s = wsum[lane];
        int si = s;
#pragma unroll
        for (int o = 1; o < 32; o <<= 1) {
            int t = __shfl_up_sync(0xffffffffu, si, o);
            if (lane >= o) si += t;
        }
        wsum[lane] = si - s;
    }
    __syncthreads();
    int warpoff = wsum[w];
    if (i < N_NODES) {
        int excl = s_boff + warpoff + inc - v;
        g_rowptr[i] = excl;
        g_fill[i]   = excl;
    }
    if (blockIdx.x == NB - 1 && tid == 1023) {
        g_rowptr[N_NODES] = s_boff + warpoff + inc;
    }
}

// Edge record stores col*32 so the SpMM gather address is a single IADD.
__global__ void k_bin(const int* __restrict__ ei) {
    int e = blockIdx.x * blockDim.x + threadIdx.x;
    if (e >= N_EDGES) return;
    int s = ei[e];
    int d = ei[N_EDGES + e];
    float cf = g_dinv[s] * g_dinv[d];
    int pos = atomicAdd(&g_fill[d], 1);
    g_edge[pos] = make_int2(s * 32, __float_as_int(cf));
}

// ---------------- tf32 MMA GEMM (3xtf32 split for fp32 accuracy) ----------------
__device__ __forceinline__ uint32_t f2tf(float v) {
    uint32_t r;
    asm("cvt.rna.tf32.f32 %0, %1;" : "=r"(r) : "f"(v));
    return r;
}
__device__ __forceinline__ void split_tf(float v, uint32_t& hi, uint32_t& lo) {
    hi = f2tf(v);
    lo = f2tf(v - __uint_as_float(hi));
}
__device__ __forceinline__ void mma8(float4& d, const uint32_t* a, uint32_t b0, uint32_t b1) {
    asm volatile(
        "mma.sync.aligned.m16n8k8.row.col.f32.tf32.tf32.f32 "
        "{%0,%1,%2,%3}, {%4,%5,%6,%7}, {%8,%9}, {%0,%1,%2,%3};"
        : "+f"(d.x), "+f"(d.y), "+f"(d.z), "+f"(d.w)
        : "r"(a[0]), "r"(a[1]), "r"(a[2]), "r"(a[3]), "r"(b0), "r"(b1));
}

// H = X @ W (100000x64 @ 64x64). 128 threads = 4 warps; 16 rows/warp.
// Writes fp32 g_h and half2 g_hh (both unscaled). No CSR dependency.
template <int SRC>  // 0: X = input x, 1: X = g_t
__global__ void __launch_bounds__(128) k_gemm(const float* __restrict__ Xin,
                                              const float* __restrict__ W) {
    __shared__ __align__(16) float sX[64 * 68];
    __shared__ __align__(16) float sW[64 * 72];
    const float* X = (SRC == 0) ? Xin : (const float*)g_t;
    int tid = threadIdx.x, warp = tid >> 5, lane = tid & 31;
    int g = lane >> 2, tq = lane & 3;
    int rowbase = blockIdx.x * 64;

    for (int i = tid; i < 1024; i += 128) {
        int k = i >> 4, c4 = (i & 15) << 2;
        float4 w = reinterpret_cast<const float4*>(W)[i];
        *reinterpret_cast<float4*>(&sW[k * 72 + c4]) = w;
    }
    for (int i = tid; i < 1024; i += 128) {
        int r = i >> 4, c4i = i & 15;
        int gr = rowbase + r;
        float4 v = (gr < N_NODES)
                       ? reinterpret_cast<const float4*>(X + (size_t)gr * D)[c4i]
                       : make_float4(0.f, 0.f, 0.f, 0.f);
        *reinterpret_cast<float4*>(&sX[r * 68 + (c4i << 2)]) = v;
    }
    __syncthreads();

    int wr = warp * 16;
    float4 acc[8];
#pragma unroll
    for (int nt = 0; nt < 8; nt++) acc[nt] = make_float4(0.f, 0.f, 0.f, 0.f);

#pragma unroll
    for (int kt = 0; kt < 8; kt++) {
        uint32_t ah[4], al[4];
        {
            float a0 = sX[(wr + g) * 68 + kt * 8 + tq];
            float a1 = sX[(wr + g + 8) * 68 + kt * 8 + tq];
            float a2 = sX[(wr + g) * 68 + kt * 8 + tq + 4];
            float a3 = sX[(wr + g + 8) * 68 + kt * 8 + tq + 4];
            split_tf(a0, ah[0], al[0]);
            split_tf(a1, ah[1], al[1]);
            split_tf(a2, ah[2], al[2]);
            split_tf(a3, ah[3], al[3]);
        }
#pragma unroll
        for (int nt = 0; nt < 8; nt++) {
            float b0f = sW[(kt * 8 + tq) * 72 + nt * 8 + g];
            float b1f = sW[(kt * 8 + tq + 4) * 72 + nt * 8 + g];
            uint32_t bh0, bl0, bh1, bl1;
            split_tf(b0f, bh0, bl0);
            split_tf(b1f, bh1, bl1);
            mma8(acc[nt], ah, bh0, bh1);
            mma8(acc[nt], al, bh0, bh1);
            mma8(acc[nt], ah, bl0, bl1);
        }
    }

    int r0 = rowbase + wr + g;
    int r1 = r0 + 8;
#pragma unroll
    for (int nt = 0; nt < 8; nt++) {
        int c = nt * 8 + tq * 2;
        if (r0 < N_NODES) {
            *reinterpret_cast<float2*>(g_h + (size_t)r0 * D + c) = make_float2(acc[nt].x, acc[nt].y);
            half2 hx = __floats2half2_rn(acc[nt].x, acc[nt].y);
            g_hh[r0 * 32 + (c >> 1)] = *reinterpret_cast<uint32_t*>(&hx);
        }
        if (r1 < N_NODES) {
            *reinterpret_cast<float2*>(g_h + (size_t)r1 * D + c) = make_float2(acc[nt].z, acc[nt].w);
            half2 hx = __floats2half2_rn(acc[nt].z, acc[nt].w);
            g_hh[r1 * 32 + (c >> 1)] = *reinterpret_cast<uint32_t*>(&hx);
        }
    }
}

// ---------------- SpMM: one warp per dst row, fp16 gathers, fp32 accumulate ----------------
// R7's proven loop; edge.x holds col*32 so gather addr is g_hh + p.x + lane (one IADD).
// MODE 1: relu -> g_t. MODE 2: final -> out[row] and out[N_NODES + row] (dup copy).
template <int MODE>
__global__ void __launch_bounds__(128) k_spmm(const float* __restrict__ bias,
                                              float* __restrict__ out) {
    int warp = (blockIdx.x * blockDim.x + threadIdx.x) >> 5;
    int lane = threadIdx.x & 31;
    if (warp >= N_NODES) return;
    int row = warp;
    float di = g_dinv[row];
    float sc = di * di;
    float2 hv = reinterpret_cast<const float2*>(g_h + (size_t)row * D)[lane];
    float ax = hv.x * sc, ay = hv.y * sc;
    int e = g_rowptr[row], end = g_rowptr[row + 1];
    for (; e + 8 <= end; e += 8) {
        int2 p[8];
        uint32_t v[8];
#pragma unroll
        for (int j = 0; j < 8; j++) p[j] = g_edge[e + j];
#pragma unroll
        for (int j = 0; j < 8; j++) v[j] = g_hh[p[j].x + lane];
#pragma unroll
        for (int j = 0; j < 8; j++) {
            float2 f = __half22float2(*reinterpret_cast<half2*>(&v[j]));
            float c = __int_as_float(p[j].y);
            ax += f.x * c;
            ay += f.y * c;
        }
    }
    for (; e < end; e++) {
        int2 p = g_edge[e];
        uint32_t vv = g_hh[p.x + lane];
        float2 f = __half22float2(*reinterpret_cast<half2*>(&vv));
        float c = __int_as_float(p.y);
        ax += f.x * c;
        ay += f.y * c;
    }
    float2 bv = reinterpret_cast<const float2*>(bias)[lane];
    ax += bv.x;
    ay += bv.y;
    if (MODE == 1) {
        float2 r = make_float2(fmaxf(ax, 0.f), fmaxf(ay, 0.f));
        reinterpret_cast<float2*>(g_t + (size_t)row * D)[lane] = r;
    } else {
        float2 r = make_float2(ax, ay);
        reinterpret_cast<float2*>(out + (size_t)row * D)[lane] = r;
        reinterpret_cast<float2*>(out + (size_t)(N_NODES + row) * D)[lane] = r;
    }
}

extern "C" void kernel_launch(void* const* d_in, const int* in_sizes, int n_in,
                              void* d_out, int out_size) {
    const float* x  = (const float*)d_in[0];
    const int*   ei = (const int*)d_in[1];
    const float* W1 = (const float*)d_in[2];
    const float* b1 = (const float*)d_in[3];
    const float* W2 = (const float*)d_in[4];
    const float* b2 = (const float*)d_in[5];
    float* out = (float*)d_out;

    static cudaStream_t s1 = nullptr;
    static cudaEvent_t ev_fork = nullptr, ev_join = nullptr;
    if (s1 == nullptr) {
        cudaStreamCreateWithFlags(&s1, cudaStreamNonBlocking);
        cudaEventCreateWithFlags(&ev_fork, cudaEventDisableTiming);
        cudaEventCreateWithFlags(&ev_join, cudaEventDisableTiming);
    }

    void* cnt_ptr = nullptr;
    cudaGetSymbolAddress(&cnt_ptr, g_cnt);

    // Fork: gemm0 runs on s1 concurrently with the CSR build on the main stream.
    cudaEventRecord(ev_fork, 0);
    cudaStreamWaitEvent(s1, ev_fork, 0);
    k_gemm<0><<<(N_NODES + 63) / 64, 128, 0, s1>>>(x, W1);      // g_h/g_hh = x @ W1
    cudaEventRecord(ev_join, s1);

    // CSR build chain on the main stream.
    cudaMemsetAsync(cnt_ptr, 0, N_NODES * sizeof(int));
    k_hist<<<(N_EDGES + 255) / 256, 256>>>(ei);
    k_reduce<<<NB, 1024>>>();
    k_scanf<<<NB, 1024>>>();
    k_bin<<<(N_EDGES + 255) / 256, 256>>>(ei);

    // Join: spmm1 needs both the CSR and gemm0's output.
    cudaStreamWaitEvent(0, ev_join, 0);
    k_spmm<1><<<(N_NODES * 32 + 127) / 128, 128>>>(b1, out);    // g_t = relu(gcn1)
    k_gemm<1><<<(N_NODES + 63) / 64, 128>>>(x, W2);             // g_h/g_hh = g_t @ W2
    k_spmm<2><<<(N_NODES * 32 + 127) / 128, 128>>>(b2, out);    // out = [h; h]
}